// round 15
// baseline (speedup 1.0000x reference)
#include <cuda_runtime.h>
#include <math.h>
#include <stdint.h>

#define N_SLOTS 16384
#define MD      512
#define CTRL    1024
#define OUTF    (3*MD + 6)   // 1542
#define NKROWS  (MD + 6)     // 518: rows needed before k_sim
#define EPSF    1e-16f

// ---- scratch (device globals: no allocation allowed) ----
__device__ float g_o[MD + 6];     // k (512) + 6 scalars
__device__ float g_e[MD];
__device__ float g_a[MD];
__device__ float g_expwc[N_SLOTS];
__device__ float g_wp[N_SLOTS];
__device__ float g_partialB[1024];
__device__ float g_partialC[64];

__device__ __forceinline__ float softplusf(float x) {
    return x > 20.f ? x : log1pf(__expf(x));
}

__device__ __forceinline__ float warp_dot_row(const float4* __restrict__ W4,
                                              const float4* __restrict__ e4,
                                              int lane) {
    float sum = 0.f;
#pragma unroll
    for (int j = 0; j < 8; j++) {
        float4 wv = W4[lane + 32*j];
        float4 ev = e4[lane + 32*j];
        sum += wv.x*ev.x + wv.y*ev.y + wv.z*ev.z + wv.w*ev.w;
    }
#pragma unroll
    for (int off = 16; off; off >>= 1) sum += __shfl_down_sync(0xffffffffu, sum, off);
    return sum;
}

// ---- K1: k + scalar rows only (518 rows) -> g_o. One warp per row. ----
__global__ void k_proj(const float* __restrict__ emb,
                       const float* __restrict__ W,
                       const float* __restrict__ b) {
    int warp = threadIdx.x >> 5;
    int lane = threadIdx.x & 31;
    int row  = blockIdx.x * 4 + warp;
    if (row < NKROWS) {
        float sum = warp_dot_row((const float4*)(W + (size_t)row * CTRL),
                                 (const float4*)emb, lane);
        if (lane == 0) g_o[row] = sum + b[row];
    }
    cudaTriggerProgrammaticLaunchCompletion();
}

// ---- K2 (PDL after k_proj): blocks [0,64): project e/a rows — inputs only,
//      NO sync: fully concurrent with k_proj. blocks [64,1088): sim; preamble
//      front-batches mem loads (input-only), then grid-dep sync, then g_o. ----
__global__ void k_sim(const float* __restrict__ mem,
                      const float* __restrict__ emb,
                      const float* __restrict__ W,
                      const float* __restrict__ b) {
    int tid = threadIdx.x;
    int wid = tid >> 5, lane = tid & 31;

    if (blockIdx.x < 64) {
        // ---- e/a projection: rows NKROWS + bid*16 + [0,16). Inputs only. ----
        int r0 = NKROWS + blockIdx.x * 16;
#pragma unroll
        for (int h = 0; h < 2; h++) {
            int row = r0 + wid * 2 + h;
            float sum = warp_dot_row((const float4*)(W + (size_t)row * CTRL),
                                     (const float4*)emb, lane);
            if (lane == 0) {
                float o = sum + b[row];
                if (row < 2*MD + 6) g_e[row - NKROWS] = o;
                else                g_a[row - (2*MD + 6)] = o;
            }
        }
        cudaTriggerProgrammaticLaunchCompletion();
        return;
    }
    int sbid = blockIdx.x - 64;   // 0..1023

    __shared__ float sk[MD];
    __shared__ float sred[16];
    __shared__ float s_beta, s_knorm;

    // PREAMBLE: front-batch the 8 global row loads (input mem only)
    int row0 = sbid * 16 + wid;        // rows row0 and row0+8
    const float4* mA = (const float4*)(mem + (size_t)row0 * MD);
    const float4* mB = (const float4*)(mem + (size_t)(row0 + 8) * MD);
    float4 va[4], vb[4];
#pragma unroll
    for (int j = 0; j < 4; j++) va[j] = mA[lane + 32*j];
#pragma unroll
    for (int j = 0; j < 4; j++) vb[j] = mB[lane + 32*j];

    cudaGridDependencySynchronize();   // k_proj results now visible

    float ksq = 0.f;
#pragma unroll
    for (int i = tid; i < MD; i += 256) { float v = g_o[i]; sk[i] = v; ksq += v*v; }
#pragma unroll
    for (int off = 16; off; off >>= 1) ksq += __shfl_down_sync(0xffffffffu, ksq, off);
    if (lane == 0) sred[wid] = ksq;
    __syncthreads();
    if (tid == 0) {
        float s = 0.f;
#pragma unroll
        for (int i = 0; i < 8; i++) s += sred[i];
        s_knorm = sqrtf(s);
        s_beta  = softplusf(g_o[MD]);
    }
    __syncthreads();   // sk + s_beta/s_knorm ready

    const float4* k4 = (const float4*)sk;
    float dotA = 0.f, nrmA = 0.f, dotB = 0.f, nrmB = 0.f;
#pragma unroll
    for (int j = 0; j < 4; j++) {
        float4 kv = k4[lane + 32*j];
        dotA += va[j].x*kv.x + va[j].y*kv.y + va[j].z*kv.z + va[j].w*kv.w;
        nrmA += va[j].x*va[j].x + va[j].y*va[j].y + va[j].z*va[j].z + va[j].w*va[j].w;
        dotB += vb[j].x*kv.x + vb[j].y*kv.y + vb[j].z*kv.z + vb[j].w*kv.w;
        nrmB += vb[j].x*vb[j].x + vb[j].y*vb[j].y + vb[j].z*vb[j].z + vb[j].w*vb[j].w;
    }
#pragma unroll
    for (int off = 16; off; off >>= 1) {
        dotA += __shfl_down_sync(0xffffffffu, dotA, off);
        nrmA += __shfl_down_sync(0xffffffffu, nrmA, off);
        dotB += __shfl_down_sync(0xffffffffu, dotB, off);
        nrmB += __shfl_down_sync(0xffffffffu, nrmB, off);
    }
    if (lane == 0) {
        // sim in [-1,1], beta = softplus(~N(0,1)) modest: exp cannot overflow
        float exA = __expf(s_beta * dotA / (s_knorm * sqrtf(nrmA) + EPSF));
        float exB = __expf(s_beta * dotB / (s_knorm * sqrtf(nrmB) + EPSF));
        g_expwc[row0]     = exA;
        g_expwc[row0 + 8] = exB;
        sred[wid]     = exA;
        sred[wid + 8] = exB;
    }
    __syncthreads();
    if (tid == 0) {
        float s = 0.f;
#pragma unroll
        for (int i = 0; i < 16; i++) s += sred[i];
        g_partialB[sbid] = s;
    }
    cudaTriggerProgrammaticLaunchCompletion();
}

// ---- K3 (PDL after k_sim): preamble prefetches w_prev (input-only). ----
__global__ void k_shiftpow(const float* __restrict__ w_prev) {
    __shared__ float red[256];
    __shared__ float sc[6];   // ise, g, s0, s1, s2, gamma
    int tid = threadIdx.x;
    int i = blockIdx.x * 256 + tid;
    int im = (i == 0) ? N_SLOTS-1 : i-1;
    int ip = (i == N_SLOTS-1) ? 0 : i+1;

    // PREAMBLE: input-only loads
    float wpm = w_prev[im], wpc = w_prev[i], wpp = w_prev[ip];

    cudaGridDependencySynchronize();   // k_sim results now visible

    float s = 0.f;
#pragma unroll
    for (int j = 0; j < 4; j++) s += g_partialB[tid + 256*j];
    red[tid] = s;
    __syncthreads();
    for (int st = 128; st; st >>= 1) { if (tid < st) red[tid] += red[tid+st]; __syncthreads(); }
    if (tid == 0) {
        sc[0] = 1.f / red[0];
        sc[1] = 1.f / (1.f + __expf(-g_o[MD+1]));
        float x0 = g_o[MD+2], x1 = g_o[MD+3], x2 = g_o[MD+4];
        float m  = fmaxf(x0, fmaxf(x1, x2));
        float e0 = __expf(x0-m), e1 = __expf(x1-m), e2 = __expf(x2-m);
        float inv = 1.f / (e0 + e1 + e2);
        sc[2] = e0*inv; sc[3] = e1*inv; sc[4] = e2*inv;
        sc[5] = 1.f + softplusf(g_o[MD+5]);
    }
    __syncthreads();

    float ise = sc[0], gg = sc[1], s0 = sc[2], s1 = sc[3], s2 = sc[4], gamma = sc[5];
    float omg = 1.f - gg;
    float wgm = gg * g_expwc[im] * ise + omg * wpm;
    float wgc = gg * g_expwc[i ] * ise + omg * wpc;
    float wgp = gg * g_expwc[ip] * ise + omg * wpp;
    float ws = s0*wgm + s1*wgc + s2*wgp;
    float wp = exp2f(gamma * __log2f(ws + EPSF));   // ws+EPS > 0 always
    g_wp[i] = wp;
    red[tid] = wp;
    __syncthreads();
    for (int st = 128; st; st >>= 1) { if (tid < st) red[tid] += red[tid+st]; __syncthreads(); }
    if (tid == 0) g_partialC[blockIdx.x] = red[0];
    cudaTriggerProgrammaticLaunchCompletion();
}

// ---- K4 (PDL after k_shiftpow): preamble = all 8 mem row loads (input-only);
//      barrier-free; 16 rows/block, 8 rows/thread (empirical optimum). ----
__global__ void k_update(const float* __restrict__ mem, float* __restrict__ out) {
    int tid  = threadIdx.x;
    int lane = tid & 31;
    int base = blockIdx.x * 16;
    int c    = tid & 127;   // float4 column
    int half = tid >> 7;    // 0/1 (warp-uniform)

    // PREAMBLE: batch all 8 independent row loads (input mem only)
    float4 m[8];
#pragma unroll
    for (int it = 0; it < 8; it++) {
        int row = base + half + 2*it;
        m[it] = ((const float4*)(mem + (size_t)row * MD))[c];
    }

    cudaGridDependencySynchronize();   // k_shiftpow (and chain) results visible

    float4 e = ((const float4*)g_e)[c];
    float4 a = ((const float4*)g_a)[c];

    // warp-redundant deterministic reduce of 64 wp-partials (no barriers)
    float s = g_partialC[lane] + g_partialC[lane + 32];
#pragma unroll
    for (int off = 16; off; off >>= 1) s += __shfl_xor_sync(0xffffffffu, s, off);
    float inv = 1.f / s;

    // this warp's 8 row-weights: ONE predicated load, then shfl broadcast
    float wp_l = (lane < 8) ? g_wp[base + half + 2*lane] : 0.f;
    float wv[8];
#pragma unroll
    for (int it = 0; it < 8; it++) wv[it] = __shfl_sync(0xffffffffu, wp_l, it) * inv;

    if (tid < 16) out[base + tid] = g_wp[base + tid] * inv;

    float* nm = out + N_SLOTS;
#pragma unroll
    for (int it = 0; it < 8; it++) {
        int row = base + half + 2*it;
        float4 r;
        r.x = m[it].x * (1.f - wv[it]*e.x) + wv[it]*a.x;
        r.y = m[it].y * (1.f - wv[it]*e.y) + wv[it]*a.y;
        r.z = m[it].z * (1.f - wv[it]*e.z) + wv[it]*a.z;
        r.w = m[it].w * (1.f - wv[it]*e.w) + wv[it]*a.w;
        __stcs((float4*)(nm + (size_t)row * MD) + c, r);   // streaming: never re-read
    }
}

extern "C" void kernel_launch(void* const* d_in, const int* in_sizes, int n_in,
                              void* d_out, int out_size) {
    const float* emb    = (const float*)d_in[0];   // (1, 1024)
    const float* w_prev = (const float*)d_in[1];   // (1, 16384)
    const float* mem    = (const float*)d_in[2];   // (16384, 512)
    const float* W      = (const float*)d_in[3];   // (1542, 1024)
    const float* b      = (const float*)d_in[4];   // (1542,)
    float* out = (float*)d_out;                    // [w(16384) | new_memory(16384*512)]

    k_proj<<<(NKROWS + 3) / 4, 128>>>(emb, W, b);

    cudaLaunchAttribute attr[1];
    attr[0].id = cudaLaunchAttributeProgrammaticStreamSerialization;
    attr[0].val.programmaticStreamSerializationAllowed = 1;

    {   // k_sim with PDL
        cudaLaunchConfig_t cfg = {};
        cfg.gridDim = dim3(64 + 1024); cfg.blockDim = dim3(256);
        cfg.stream = 0; cfg.attrs = attr; cfg.numAttrs = 1;
        cudaLaunchKernelEx(&cfg, k_sim, mem, emb, W, b);
    }
    {   // k_shiftpow with PDL
        cudaLaunchConfig_t cfg = {};
        cfg.gridDim = dim3(64); cfg.blockDim = dim3(256);
        cfg.stream = 0; cfg.attrs = attr; cfg.numAttrs = 1;
        cudaLaunchKernelEx(&cfg, k_shiftpow, w_prev);
    }
    {   // k_update with PDL
        cudaLaunchConfig_t cfg = {};
        cfg.gridDim = dim3(N_SLOTS / 16); cfg.blockDim = dim3(256);
        cfg.stream = 0; cfg.attrs = attr; cfg.numAttrs = 1;
        cudaLaunchKernelEx(&cfg, k_update, mem, out);
    }
}

// round 16
// speedup vs baseline: 1.1153x; 1.1153x over previous
#include <cuda_runtime.h>
#include <math.h>
#include <stdint.h>

#define N_SLOTS 16384
#define MD      512
#define CTRL    1024
#define OUTF    (3*MD + 6)   // 1542
#define NKROWS  (MD + 6)     // 518: rows needed before k_sim
#define EPSF    1e-16f

// ---- scratch (device globals: no allocation allowed) ----
__device__ float g_o[MD + 6];     // k (512) + 6 scalars
__device__ float g_e[MD];
__device__ float g_a[MD];
__device__ float g_expwc[N_SLOTS];
__device__ float g_wp[N_SLOTS];
__device__ float g_partialB[1024];
__device__ float g_partialC[64];

__device__ __forceinline__ float softplusf(float x) {
    return x > 20.f ? x : log1pf(__expf(x));
}

__device__ __forceinline__ float warp_dot_row(const float4* __restrict__ W4,
                                              const float4* __restrict__ e4,
                                              int lane) {
    float sum = 0.f;
#pragma unroll
    for (int j = 0; j < 8; j++) {
        float4 wv = W4[lane + 32*j];
        float4 ev = e4[lane + 32*j];
        sum += wv.x*ev.x + wv.y*ev.y + wv.z*ev.z + wv.w*ev.w;
    }
#pragma unroll
    for (int off = 16; off; off >>= 1) sum += __shfl_down_sync(0xffffffffu, sum, off);
    return sum;
}

// ---- K1: k + scalar rows only (518 rows) -> g_o. One warp per row. ----
__global__ void k_proj(const float* __restrict__ emb,
                       const float* __restrict__ W,
                       const float* __restrict__ b) {
    int warp = threadIdx.x >> 5;
    int lane = threadIdx.x & 31;
    int row  = blockIdx.x * 4 + warp;
    if (row >= NKROWS) return;
    float sum = warp_dot_row((const float4*)(W + (size_t)row * CTRL),
                             (const float4*)emb, lane);
    if (lane == 0) g_o[row] = sum + b[row];
}

// ---- K2: blocks [0,64): project e/a rows (16 rows/block) — FIRST so they
//      launch in wave 1 and hide under the sim DRAM stream.
//      blocks [64,1088): cosine sim + exp(beta*sim), 16 rows/block,
//      2 rows/warp with 8 front-batched LDG.128/thread. ----
__global__ void k_sim(const float* __restrict__ mem,
                      const float* __restrict__ emb,
                      const float* __restrict__ W,
                      const float* __restrict__ b) {
    int tid = threadIdx.x;
    int wid = tid >> 5, lane = tid & 31;

    if (blockIdx.x < 64) {
        // ---- e/a projection: rows NKROWS + bid*16 + [0,16) ----
        int r0 = NKROWS + blockIdx.x * 16;
#pragma unroll
        for (int h = 0; h < 2; h++) {
            int row = r0 + wid * 2 + h;
            float sum = warp_dot_row((const float4*)(W + (size_t)row * CTRL),
                                     (const float4*)emb, lane);
            if (lane == 0) {
                float o = sum + b[row];
                if (row < 2*MD + 6) g_e[row - NKROWS] = o;
                else                g_a[row - (2*MD + 6)] = o;
            }
        }
        return;
    }
    int sbid = blockIdx.x - 64;   // 0..1023

    __shared__ float sk[MD];
    __shared__ float sred[16];
    __shared__ float s_beta, s_knorm;

    // front-batch the 8 global row loads (independent of k/smem work)
    int row0 = sbid * 16 + wid;        // rows row0 and row0+8
    const float4* mA = (const float4*)(mem + (size_t)row0 * MD);
    const float4* mB = (const float4*)(mem + (size_t)(row0 + 8) * MD);
    float4 va[4], vb[4];
#pragma unroll
    for (int j = 0; j < 4; j++) va[j] = mA[lane + 32*j];
#pragma unroll
    for (int j = 0; j < 4; j++) vb[j] = mB[lane + 32*j];

    float ksq = 0.f;
#pragma unroll
    for (int i = tid; i < MD; i += 256) { float v = g_o[i]; sk[i] = v; ksq += v*v; }
#pragma unroll
    for (int off = 16; off; off >>= 1) ksq += __shfl_down_sync(0xffffffffu, ksq, off);
    if (lane == 0) sred[wid] = ksq;
    __syncthreads();
    if (tid == 0) {
        float s = 0.f;
#pragma unroll
        for (int i = 0; i < 8; i++) s += sred[i];
        s_knorm = sqrtf(s);
        s_beta  = softplusf(g_o[MD]);
    }
    __syncthreads();   // sk + s_beta/s_knorm ready

    const float4* k4 = (const float4*)sk;
    float dotA = 0.f, nrmA = 0.f, dotB = 0.f, nrmB = 0.f;
#pragma unroll
    for (int j = 0; j < 4; j++) {
        float4 kv = k4[lane + 32*j];
        dotA += va[j].x*kv.x + va[j].y*kv.y + va[j].z*kv.z + va[j].w*kv.w;
        nrmA += va[j].x*va[j].x + va[j].y*va[j].y + va[j].z*va[j].z + va[j].w*va[j].w;
        dotB += vb[j].x*kv.x + vb[j].y*kv.y + vb[j].z*kv.z + vb[j].w*kv.w;
        nrmB += vb[j].x*vb[j].x + vb[j].y*vb[j].y + vb[j].z*vb[j].z + vb[j].w*vb[j].w;
    }
#pragma unroll
    for (int off = 16; off; off >>= 1) {
        dotA += __shfl_down_sync(0xffffffffu, dotA, off);
        nrmA += __shfl_down_sync(0xffffffffu, nrmA, off);
        dotB += __shfl_down_sync(0xffffffffu, dotB, off);
        nrmB += __shfl_down_sync(0xffffffffu, nrmB, off);
    }
    if (lane == 0) {
        // sim in [-1,1], beta = softplus(~N(0,1)) modest: exp cannot overflow
        float exA = __expf(s_beta * dotA / (s_knorm * sqrtf(nrmA) + EPSF));
        float exB = __expf(s_beta * dotB / (s_knorm * sqrtf(nrmB) + EPSF));
        g_expwc[row0]     = exA;
        g_expwc[row0 + 8] = exB;
        sred[wid]     = exA;
        sred[wid + 8] = exB;
    }
    __syncthreads();
    if (tid == 0) {
        float s = 0.f;
#pragma unroll
        for (int i = 0; i < 16; i++) s += sred[i];
        g_partialB[sbid] = s;
    }
}

// ---- K3: interpolate + shift + sharpen. Each block redundantly reduces
//      the 1024 exp-partials and derives scalars. 64 blocks x 256. ----
__global__ void k_shiftpow(const float* __restrict__ w_prev) {
    __shared__ float red[256];
    __shared__ float sc[6];   // ise, g, s0, s1, s2, gamma
    int tid = threadIdx.x;

    float s = 0.f;
#pragma unroll
    for (int j = 0; j < 4; j++) s += g_partialB[tid + 256*j];
    red[tid] = s;
    __syncthreads();
    for (int st = 128; st; st >>= 1) { if (tid < st) red[tid] += red[tid+st]; __syncthreads(); }
    if (tid == 0) {
        sc[0] = 1.f / red[0];
        sc[1] = 1.f / (1.f + __expf(-g_o[MD+1]));
        float x0 = g_o[MD+2], x1 = g_o[MD+3], x2 = g_o[MD+4];
        float m  = fmaxf(x0, fmaxf(x1, x2));
        float e0 = __expf(x0-m), e1 = __expf(x1-m), e2 = __expf(x2-m);
        float inv = 1.f / (e0 + e1 + e2);
        sc[2] = e0*inv; sc[3] = e1*inv; sc[4] = e2*inv;
        sc[5] = 1.f + softplusf(g_o[MD+5]);
    }
    __syncthreads();

    float ise = sc[0], gg = sc[1], s0 = sc[2], s1 = sc[3], s2 = sc[4], gamma = sc[5];
    float omg = 1.f - gg;
    int i = blockIdx.x * 256 + tid;
    int im = (i == 0) ? N_SLOTS-1 : i-1;
    int ip = (i == N_SLOTS-1) ? 0 : i+1;
    float wgm = gg * g_expwc[im] * ise + omg * w_prev[im];
    float wgc = gg * g_expwc[i ] * ise + omg * w_prev[i ];
    float wgp = gg * g_expwc[ip] * ise + omg * w_prev[ip];
    float ws = s0*wgm + s1*wgc + s2*wgp;
    float wp = exp2f(gamma * __log2f(ws + EPSF));   // ws+EPS > 0 always
    g_wp[i] = wp;
    red[tid] = wp;
    __syncthreads();
    for (int st = 128; st; st >>= 1) { if (tid < st) red[tid] += red[tid+st]; __syncthreads(); }
    if (tid == 0) g_partialC[blockIdx.x] = red[0];
}

// ---- K4: memory update + w output. Barrier-free; 16 rows per 256-thread
//      block, 8 rows/thread (empirical optimum). Stores via st.global.wt
//      (write-through) to decouple the write drain from L2 read hits. ----
__global__ void k_update(const float* __restrict__ mem, float* __restrict__ out) {
    int tid  = threadIdx.x;
    int lane = tid & 31;
    int base = blockIdx.x * 16;
    int c    = tid & 127;   // float4 column
    int half = tid >> 7;    // 0/1 (warp-uniform)

    // batch all 8 independent row loads first
    float4 m[8];
#pragma unroll
    for (int it = 0; it < 8; it++) {
        int row = base + half + 2*it;
        m[it] = ((const float4*)(mem + (size_t)row * MD))[c];
    }
    float4 e = ((const float4*)g_e)[c];
    float4 a = ((const float4*)g_a)[c];

    // warp-redundant deterministic reduce of 64 wp-partials (no barriers)
    float s = g_partialC[lane] + g_partialC[lane + 32];
#pragma unroll
    for (int off = 16; off; off >>= 1) s += __shfl_xor_sync(0xffffffffu, s, off);
    float inv = 1.f / s;

    // this warp's 8 row-weights: ONE predicated load, then shfl broadcast
    float wp_l = (lane < 8) ? g_wp[base + half + 2*lane] : 0.f;
    float wv[8];
#pragma unroll
    for (int it = 0; it < 8; it++) wv[it] = __shfl_sync(0xffffffffu, wp_l, it) * inv;

    if (tid < 16) out[base + tid] = g_wp[base + tid] * inv;

    float* nm = out + N_SLOTS;
#pragma unroll
    for (int it = 0; it < 8; it++) {
        int row = base + half + 2*it;
        float4 r;
        r.x = m[it].x * (1.f - wv[it]*e.x) + wv[it]*a.x;
        r.y = m[it].y * (1.f - wv[it]*e.y) + wv[it]*a.y;
        r.z = m[it].z * (1.f - wv[it]*e.z) + wv[it]*a.z;
        r.w = m[it].w * (1.f - wv[it]*e.w) + wv[it]*a.w;
        __stwt((float4*)(nm + (size_t)row * MD) + c, r);   // write-through stream
    }
}

extern "C" void kernel_launch(void* const* d_in, const int* in_sizes, int n_in,
                              void* d_out, int out_size) {
    const float* emb    = (const float*)d_in[0];   // (1, 1024)
    const float* w_prev = (const float*)d_in[1];   // (1, 16384)
    const float* mem    = (const float*)d_in[2];   // (16384, 512)
    const float* W      = (const float*)d_in[3];   // (1542, 1024)
    const float* b      = (const float*)d_in[4];   // (1542,)
    float* out = (float*)d_out;                    // [w(16384) | new_memory(16384*512)]

    k_proj<<<(NKROWS + 3) / 4, 128>>>(emb, W, b);
    k_sim<<<64 + 1024, 256>>>(mem, emb, W, b);
    k_shiftpow<<<64, 256>>>(w_prev);
    k_update<<<N_SLOTS / 16, 256>>>(mem, out);
}

// round 17
// speedup vs baseline: 1.2241x; 1.0976x over previous
#include <cuda_runtime.h>
#include <math.h>
#include <stdint.h>

#define N_SLOTS 16384
#define MD      512
#define CTRL    1024
#define OUTF    (3*MD + 6)   // 1542
#define NKROWS  (MD + 6)     // 518: rows needed before k_sim
#define EPSF    1e-16f

// ---- scratch (device globals: no allocation allowed) ----
__device__ float g_o[MD + 6];     // k (512) + 6 scalars
__device__ float g_e[MD];
__device__ float g_a[MD];
__device__ float g_expwc[N_SLOTS];
__device__ float g_wp[N_SLOTS];
__device__ float g_partialB[1024];
__device__ float g_partialC[64];

__device__ __forceinline__ float softplusf(float x) {
    return x > 20.f ? x : log1pf(__expf(x));
}

__device__ __forceinline__ float warp_dot_row(const float4* __restrict__ W4,
                                              const float4* __restrict__ e4,
                                              int lane) {
    float sum = 0.f;
#pragma unroll
    for (int j = 0; j < 8; j++) {
        float4 wv = W4[lane + 32*j];
        float4 ev = e4[lane + 32*j];
        sum += wv.x*ev.x + wv.y*ev.y + wv.z*ev.z + wv.w*ev.w;
    }
#pragma unroll
    for (int off = 16; off; off >>= 1) sum += __shfl_down_sync(0xffffffffu, sum, off);
    return sum;
}

// ---- K1: k + scalar rows only (518 rows) -> g_o. One warp per row. ----
__global__ void k_proj(const float* __restrict__ emb,
                       const float* __restrict__ W,
                       const float* __restrict__ b) {
    int warp = threadIdx.x >> 5;
    int lane = threadIdx.x & 31;
    int row  = blockIdx.x * 4 + warp;
    if (row >= NKROWS) return;
    float sum = warp_dot_row((const float4*)(W + (size_t)row * CTRL),
                             (const float4*)emb, lane);
    if (lane == 0) g_o[row] = sum + b[row];
}

// ---- K2: blocks [0,64): project e/a rows (16 rows/block) — FIRST so they
//      launch in wave 1 and hide under the sim DRAM stream.
//      blocks [64,1088): cosine sim + exp(beta*sim), 16 rows/block,
//      2 rows/warp with 8 front-batched LDG.128/thread. ----
__global__ void k_sim(const float* __restrict__ mem,
                      const float* __restrict__ emb,
                      const float* __restrict__ W,
                      const float* __restrict__ b) {
    int tid = threadIdx.x;
    int wid = tid >> 5, lane = tid & 31;

    if (blockIdx.x < 64) {
        // ---- e/a projection: rows NKROWS + bid*16 + [0,16) ----
        int r0 = NKROWS + blockIdx.x * 16;
#pragma unroll
        for (int h = 0; h < 2; h++) {
            int row = r0 + wid * 2 + h;
            float sum = warp_dot_row((const float4*)(W + (size_t)row * CTRL),
                                     (const float4*)emb, lane);
            if (lane == 0) {
                float o = sum + b[row];
                if (row < 2*MD + 6) g_e[row - NKROWS] = o;
                else                g_a[row - (2*MD + 6)] = o;
            }
        }
        return;
    }
    int sbid = blockIdx.x - 64;   // 0..1023

    __shared__ float sk[MD];
    __shared__ float sred[16];
    __shared__ float s_beta, s_knorm;

    // front-batch the 8 global row loads (independent of k/smem work)
    int row0 = sbid * 16 + wid;        // rows row0 and row0+8
    const float4* mA = (const float4*)(mem + (size_t)row0 * MD);
    const float4* mB = (const float4*)(mem + (size_t)(row0 + 8) * MD);
    float4 va[4], vb[4];
#pragma unroll
    for (int j = 0; j < 4; j++) va[j] = mA[lane + 32*j];
#pragma unroll
    for (int j = 0; j < 4; j++) vb[j] = mB[lane + 32*j];

    float ksq = 0.f;
#pragma unroll
    for (int i = tid; i < MD; i += 256) { float v = g_o[i]; sk[i] = v; ksq += v*v; }
#pragma unroll
    for (int off = 16; off; off >>= 1) ksq += __shfl_down_sync(0xffffffffu, ksq, off);
    if (lane == 0) sred[wid] = ksq;
    __syncthreads();
    if (tid == 0) {
        float s = 0.f;
#pragma unroll
        for (int i = 0; i < 8; i++) s += sred[i];
        s_knorm = sqrtf(s);
        s_beta  = softplusf(g_o[MD]);
    }
    __syncthreads();   // sk + s_beta/s_knorm ready

    const float4* k4 = (const float4*)sk;
    float dotA = 0.f, nrmA = 0.f, dotB = 0.f, nrmB = 0.f;
#pragma unroll
    for (int j = 0; j < 4; j++) {
        float4 kv = k4[lane + 32*j];
        dotA += va[j].x*kv.x + va[j].y*kv.y + va[j].z*kv.z + va[j].w*kv.w;
        nrmA += va[j].x*va[j].x + va[j].y*va[j].y + va[j].z*va[j].z + va[j].w*va[j].w;
        dotB += vb[j].x*kv.x + vb[j].y*kv.y + vb[j].z*kv.z + vb[j].w*kv.w;
        nrmB += vb[j].x*vb[j].x + vb[j].y*vb[j].y + vb[j].z*vb[j].z + vb[j].w*vb[j].w;
    }
#pragma unroll
    for (int off = 16; off; off >>= 1) {
        dotA += __shfl_down_sync(0xffffffffu, dotA, off);
        nrmA += __shfl_down_sync(0xffffffffu, nrmA, off);
        dotB += __shfl_down_sync(0xffffffffu, dotB, off);
        nrmB += __shfl_down_sync(0xffffffffu, nrmB, off);
    }
    if (lane == 0) {
        // sim in [-1,1], beta = softplus(~N(0,1)) modest: exp cannot overflow
        float exA = __expf(s_beta * dotA / (s_knorm * sqrtf(nrmA) + EPSF));
        float exB = __expf(s_beta * dotB / (s_knorm * sqrtf(nrmB) + EPSF));
        g_expwc[row0]     = exA;
        g_expwc[row0 + 8] = exB;
        sred[wid]     = exA;
        sred[wid + 8] = exB;
    }
    __syncthreads();
    if (tid == 0) {
        float s = 0.f;
#pragma unroll
        for (int i = 0; i < 16; i++) s += sred[i];
        g_partialB[sbid] = s;
    }
}

// ---- K3: interpolate + shift + sharpen. Each block redundantly reduces
//      the 1024 exp-partials and derives scalars. 64 blocks x 256. ----
__global__ void k_shiftpow(const float* __restrict__ w_prev) {
    __shared__ float red[256];
    __shared__ float sc[6];   // ise, g, s0, s1, s2, gamma
    int tid = threadIdx.x;

    float s = 0.f;
#pragma unroll
    for (int j = 0; j < 4; j++) s += g_partialB[tid + 256*j];
    red[tid] = s;
    __syncthreads();
    for (int st = 128; st; st >>= 1) { if (tid < st) red[tid] += red[tid+st]; __syncthreads(); }
    if (tid == 0) {
        sc[0] = 1.f / red[0];
        sc[1] = 1.f / (1.f + __expf(-g_o[MD+1]));
        float x0 = g_o[MD+2], x1 = g_o[MD+3], x2 = g_o[MD+4];
        float m  = fmaxf(x0, fmaxf(x1, x2));
        float e0 = __expf(x0-m), e1 = __expf(x1-m), e2 = __expf(x2-m);
        float inv = 1.f / (e0 + e1 + e2);
        sc[2] = e0*inv; sc[3] = e1*inv; sc[4] = e2*inv;
        sc[5] = 1.f + softplusf(g_o[MD+5]);
    }
    __syncthreads();

    float ise = sc[0], gg = sc[1], s0 = sc[2], s1 = sc[3], s2 = sc[4], gamma = sc[5];
    float omg = 1.f - gg;
    int i = blockIdx.x * 256 + tid;
    int im = (i == 0) ? N_SLOTS-1 : i-1;
    int ip = (i == N_SLOTS-1) ? 0 : i+1;
    float wgm = gg * g_expwc[im] * ise + omg * w_prev[im];
    float wgc = gg * g_expwc[i ] * ise + omg * w_prev[i ];
    float wgp = gg * g_expwc[ip] * ise + omg * w_prev[ip];
    float ws = s0*wgm + s1*wgc + s2*wgp;
    float wp = exp2f(gamma * __log2f(ws + EPSF));   // ws+EPS > 0 always
    g_wp[i] = wp;
    red[tid] = wp;
    __syncthreads();
    for (int st = 128; st; st >>= 1) { if (tid < st) red[tid] += red[tid+st]; __syncthreads(); }
    if (tid == 0) g_partialC[blockIdx.x] = red[0];
}

// ---- K4: memory update + w output. Barrier-free; 16 rows per 256-thread
//      block, 8 rows/thread (empirical optimum). wp via one predicated
//      load + shfl broadcast; streaming stores. ----
__global__ void k_update(const float* __restrict__ mem, float* __restrict__ out) {
    int tid  = threadIdx.x;
    int lane = tid & 31;
    int base = blockIdx.x * 16;
    int c    = tid & 127;   // float4 column
    int half = tid >> 7;    // 0/1 (warp-uniform)

    // batch all 8 independent row loads first
    float4 m[8];
#pragma unroll
    for (int it = 0; it < 8; it++) {
        int row = base + half + 2*it;
        m[it] = ((const float4*)(mem + (size_t)row * MD))[c];
    }
    float4 e = ((const float4*)g_e)[c];
    float4 a = ((const float4*)g_a)[c];

    // warp-redundant deterministic reduce of 64 wp-partials (no barriers)
    float s = g_partialC[lane] + g_partialC[lane + 32];
#pragma unroll
    for (int off = 16; off; off >>= 1) s += __shfl_xor_sync(0xffffffffu, s, off);
    float inv = 1.f / s;

    // this warp's 8 row-weights: ONE predicated load, then shfl broadcast
    float wp_l = (lane < 8) ? g_wp[base + half + 2*lane] : 0.f;
    float wv[8];
#pragma unroll
    for (int it = 0; it < 8; it++) wv[it] = __shfl_sync(0xffffffffu, wp_l, it) * inv;

    if (tid < 16) out[base + tid] = g_wp[base + tid] * inv;

    float* nm = out + N_SLOTS;
#pragma unroll
    for (int it = 0; it < 8; it++) {
        int row = base + half + 2*it;
        float4 r;
        r.x = m[it].x * (1.f - wv[it]*e.x) + wv[it]*a.x;
        r.y = m[it].y * (1.f - wv[it]*e.y) + wv[it]*a.y;
        r.z = m[it].z * (1.f - wv[it]*e.z) + wv[it]*a.z;
        r.w = m[it].w * (1.f - wv[it]*e.w) + wv[it]*a.w;
        __stcs((float4*)(nm + (size_t)row * MD) + c, r);   // streaming: never re-read
    }
}

extern "C" void kernel_launch(void* const* d_in, const int* in_sizes, int n_in,
                              void* d_out, int out_size) {
    const float* emb    = (const float*)d_in[0];   // (1, 1024)
    const float* w_prev = (const float*)d_in[1];   // (1, 16384)
    const float* mem    = (const float*)d_in[2];   // (16384, 512)
    const float* W      = (const float*)d_in[3];   // (1542, 1024)
    const float* b      = (const float*)d_in[4];   // (1542,)
    float* out = (float*)d_out;                    // [w(16384) | new_memory(16384*512)]

    k_proj<<<(NKROWS + 3) / 4, 128>>>(emb, W, b);
    k_sim<<<64 + 1024, 256>>>(mem, emb, W, b);
    k_shiftpow<<<64, 256>>>(w_prev);
    k_update<<<N_SLOTS / 16, 256>>>(mem, out);
}